// round 4
// baseline (speedup 1.0000x reference)
#include <cuda_runtime.h>
#include <cuda_bf16.h>

// B=64, H=W=1024, patch=64 -> 16x16 = 256 patches/img.
// final = mean_b( max_patch( mean_{64x64} |o - t| ) )
//
// One block per (image, patch-row-strip): 64 rows x 1024 cols = 512 KB of
// reads, fully contiguous per row. Thread tid owns float4-column tid; all its
// 64 row-values belong to patch pw = tid>>4, so the patch sum is a 16-lane
// shuffle reduce + one atomicMax straight into the per-image max.

#define B 64
#define HW 1024
#define P 64
#define NSTRIPS 16                    // patch rows per image
#define NBLOCKS (B * NSTRIPS)         // 1024
#define PATCH_ELEMS (P * P)           // 4096

__device__ unsigned int g_img_max[B]; // zero-init; re-zeroed by last block
__device__ unsigned int g_counter;    // monotone, wrap-safe

__global__ __launch_bounds__(256) void patch_loss_strip_kernel(
    const float* __restrict__ o, const float* __restrict__ t,
    float* __restrict__ out)
{
    const int blk = blockIdx.x;           // 0..1023
    const int img = blk >> 4;
    const int ph  = blk & 15;

    const size_t base = (size_t)img * (HW * HW) + (size_t)ph * (P * HW);
    const float4* __restrict__ o4 = reinterpret_cast<const float4*>(o + base);
    const float4* __restrict__ t4 = reinterpret_cast<const float4*>(t + base);

    const int tid = threadIdx.x;          // float4 column 0..255
    float acc = 0.0f;

    // 64 rows, row stride = 256 float4. Unroll 8 -> 16 LDG.128 in flight.
#pragma unroll 8
    for (int r = 0; r < 64; r++) {
        int off = r * 256 + tid;
        float4 a = __ldcs(&o4[off]);
        float4 b = __ldcs(&t4[off]);
        acc += fabsf(a.x - b.x) + fabsf(a.y - b.y)
             + fabsf(a.z - b.z) + fabsf(a.w - b.w);
    }

    // Reduce within 16-lane group (one patch): xor of bits 0..3 only.
#pragma unroll
    for (int s = 8; s > 0; s >>= 1)
        acc += __shfl_xor_sync(0xFFFFFFFFu, acc, s);

    __shared__ bool s_is_last;
    if ((tid & 15) == 0) {
        // acc is the patch sum (>= 0): float bits monotone as unsigned
        atomicMax(&g_img_max[img], __float_as_uint(acc));
    }
    __syncthreads();           // all 16 atomics of this block issued
    if (tid == 0) {
        __threadfence();
        unsigned int old = atomicAdd(&g_counter, 1u);
        s_is_last = ((old % NBLOCKS) == (NBLOCKS - 1));
    }
    __syncthreads();

    if (s_is_last) {
        __threadfence();
        __shared__ float warp_sums[2];
        const int lane = tid & 31;
        const int wid = tid >> 5;
        if (wid < 2) {
            int i = wid * 32 + lane;                      // 0..63
            unsigned int bits = atomicOr(&g_img_max[i], 0u);
            float m = __uint_as_float(bits);
#pragma unroll
            for (int s = 16; s > 0; s >>= 1)
                m += __shfl_xor_sync(0xFFFFFFFFu, m, s);
            if (lane == 0) warp_sums[wid] = m;
        }
        __syncthreads();
        if (tid == 0)
            *out = (warp_sums[0] + warp_sums[1])
                 * (1.0f / (float)PATCH_ELEMS / (float)B);
        __syncthreads();
        if (tid < B) g_img_max[tid] = 0u;   // reset for next replay
    }
}

extern "C" void kernel_launch(void* const* d_in, const int* in_sizes, int n_in,
                              void* d_out, int out_size)
{
    const float* o = (const float*)d_in[0];
    const float* t = (const float*)d_in[1];
    float* out = (float*)d_out;
    patch_loss_strip_kernel<<<NBLOCKS, 256>>>(o, t, out);
}

// round 5
// speedup vs baseline: 1.1565x; 1.1565x over previous
#include <cuda_runtime.h>
#include <cuda_bf16.h>

// B=64, H=W=1024, patch=64 -> 16x16 = 256 patches/img, 16384 patches total.
// final = mean_b( max_patch( mean_{64x64} |o - t| ) )
// One block per patch; 256 threads x 16 elems. All 8 float4 loads per thread
// are issued before any arithmetic (front-batched MLP=8), 4 independent accs.

#define B 64
#define HW 1024
#define P 64
#define NPATCH_PER_IMG 256
#define NPATCH_TOTAL (B * NPATCH_PER_IMG)   // 16384
#define PATCH_ELEMS (P * P)                 // 4096

__device__ unsigned int g_img_max[B];   // zero-init; re-zeroed by last block
__device__ unsigned int g_counter;      // monotone, wrap-safe

__global__ __launch_bounds__(256, 4) void patch_loss_fused_kernel(
    const float* __restrict__ o, const float* __restrict__ t,
    float* __restrict__ out)
{
    const int patch = blockIdx.x;           // 0..16383
    const int img = patch >> 8;
    const int pid = patch & 255;
    const int ph = pid >> 4;
    const int pw = pid & 15;

    const size_t base = (size_t)img * (HW * HW) + (size_t)ph * (P * HW) + (size_t)pw * P;
    const float4* __restrict__ o4 = reinterpret_cast<const float4*>(o + base);
    const float4* __restrict__ t4 = reinterpret_cast<const float4*>(t + base);

    const int tid = threadIdx.x;
    // thread's float4 idx i*256+tid -> row=(idx>>4), col=(idx&15)
    // off = row*256 + col = ((tid>>4)<<8) + (tid&15) + i*4096
    const int off0 = ((tid >> 4) << 8) + (tid & 15);

    // Front-batch ALL loads (8 x LDG.128 outstanding), then accumulate.
    float4 a0 = __ldcs(&o4[off0]);
    float4 a1 = __ldcs(&o4[off0 + 4096]);
    float4 a2 = __ldcs(&o4[off0 + 8192]);
    float4 a3 = __ldcs(&o4[off0 + 12288]);
    float4 b0 = __ldcs(&t4[off0]);
    float4 b1 = __ldcs(&t4[off0 + 4096]);
    float4 b2 = __ldcs(&t4[off0 + 8192]);
    float4 b3 = __ldcs(&t4[off0 + 12288]);

    float s0 = fabsf(a0.x - b0.x) + fabsf(a0.y - b0.y)
             + fabsf(a0.z - b0.z) + fabsf(a0.w - b0.w);
    float s1 = fabsf(a1.x - b1.x) + fabsf(a1.y - b1.y)
             + fabsf(a1.z - b1.z) + fabsf(a1.w - b1.w);
    float s2 = fabsf(a2.x - b2.x) + fabsf(a2.y - b2.y)
             + fabsf(a2.z - b2.z) + fabsf(a2.w - b2.w);
    float s3 = fabsf(a3.x - b3.x) + fabsf(a3.y - b3.y)
             + fabsf(a3.z - b3.z) + fabsf(a3.w - b3.w);
    float acc = (s0 + s1) + (s2 + s3);

    // warp reduce
#pragma unroll
    for (int s = 16; s > 0; s >>= 1)
        acc += __shfl_xor_sync(0xFFFFFFFFu, acc, s);

    __shared__ float warp_sums[8];
    __shared__ bool s_is_last;
    const int lane = tid & 31;
    const int wid = tid >> 5;
    if (lane == 0) warp_sums[wid] = acc;
    __syncthreads();

    if (tid == 0) {
        float v = warp_sums[0] + warp_sums[1] + warp_sums[2] + warp_sums[3]
                + warp_sums[4] + warp_sums[5] + warp_sums[6] + warp_sums[7];
        atomicMax(&g_img_max[img], __float_as_uint(v));  // v >= 0: bits monotone
        __threadfence();
        unsigned int old = atomicAdd(&g_counter, 1u);
        s_is_last = ((old % NPATCH_TOTAL) == (NPATCH_TOTAL - 1));
    }
    __syncthreads();

    if (s_is_last) {
        __threadfence();
        if (wid < 2) {
            int i = wid * 32 + lane;                      // 0..63
            unsigned int bits = atomicOr(&g_img_max[i], 0u);
            float m = __uint_as_float(bits);
#pragma unroll
            for (int s = 16; s > 0; s >>= 1)
                m += __shfl_xor_sync(0xFFFFFFFFu, m, s);
            if (lane == 0) warp_sums[wid] = m;
        }
        __syncthreads();
        if (tid == 0)
            *out = (warp_sums[0] + warp_sums[1])
                 * (1.0f / (float)PATCH_ELEMS / (float)B);
        __syncthreads();
        if (tid < B) g_img_max[tid] = 0u;   // reset for next replay
    }
}

extern "C" void kernel_launch(void* const* d_in, const int* in_sizes, int n_in,
                              void* d_out, int out_size)
{
    const float* o = (const float*)d_in[0];
    const float* t = (const float*)d_in[1];
    float* out = (float*)d_out;
    patch_loss_fused_kernel<<<NPATCH_TOTAL, 256>>>(o, t, out);
}

// round 6
// speedup vs baseline: 1.1583x; 1.0016x over previous
#include <cuda_runtime.h>
#include <cuda_bf16.h>

// B=64, H=W=1024, patch=64 -> 16x16 = 256 patches/img.
// final = mean_b( max_patch( mean_{64x64} |o - t| ) )
//
// One block per PAIR of horizontally adjacent patches: grid = 64*16*8 = 8192,
// 256 threads. Thread tid owns float4-col (tid&31) of the 128-col pair and
// row group (tid>>5); it loads 8 rows from each tensor, all 16 LDG.128
// front-batched for MLP. Lane==col, so lanes 0-15 hold patch0, 16-31 patch1:
// a 4-step half-warp shuffle gives both patch sums per warp.

#define B 64
#define HW 1024
#define P 64
#define NBLOCKS (B * 16 * 8)            // 8192
#define PATCH_ELEMS (P * P)             // 4096

__device__ unsigned int g_img_max[B];   // zero-init; re-zeroed by last block
__device__ unsigned int g_counter;      // monotone, wrap-safe

__global__ __launch_bounds__(256, 3) void patch_loss_pair_kernel(
    const float* __restrict__ o, const float* __restrict__ t,
    float* __restrict__ out)
{
    const int blk  = blockIdx.x;          // 0..8191
    const int img  = blk >> 7;            // /128
    const int ph   = (blk >> 3) & 15;
    const int pair = blk & 7;             // patch-col pair 0..7

    // pair covers cols [pair*128, pair*128+128)
    const size_t base = (size_t)img * (HW * HW) + (size_t)ph * (P * HW)
                      + (size_t)pair * 128;
    const float4* __restrict__ o4 = reinterpret_cast<const float4*>(o + base);
    const float4* __restrict__ t4 = reinterpret_cast<const float4*>(t + base);

    const int tid = threadIdx.x;
    const int col = tid & 31;             // float4 col within pair (== lane)
    const int rg  = tid >> 5;             // row group 0..7

    // rows handled: rg + i*8, i = 0..7; row stride = 256 float4
    const int off0 = rg * 256 + col;

    float4 av[8], bv[8];
#pragma unroll
    for (int i = 0; i < 8; i++) av[i] = __ldcs(&o4[off0 + i * 2048]);
#pragma unroll
    for (int i = 0; i < 8; i++) bv[i] = __ldcs(&t4[off0 + i * 2048]);

    float acc = 0.0f;
#pragma unroll
    for (int i = 0; i < 8; i++) {
        acc += fabsf(av[i].x - bv[i].x) + fabsf(av[i].y - bv[i].y)
             + fabsf(av[i].z - bv[i].z) + fabsf(av[i].w - bv[i].w);
    }

    // Reduce within each 16-lane half (one patch per half).
#pragma unroll
    for (int s = 8; s > 0; s >>= 1)
        acc += __shfl_xor_sync(0xFFFFFFFFu, acc, s);

    __shared__ float warp_sums[2][8];
    __shared__ bool s_is_last;
    const int lane = tid & 31;
    const int wid = tid >> 5;
    if (lane == 0)  warp_sums[0][wid] = acc;   // patch0 partial (rows of rg)
    if (lane == 16) warp_sums[1][wid] = acc;   // patch1 partial
    __syncthreads();

    if (tid == 0) {
        float v0 = 0.f, v1 = 0.f;
#pragma unroll
        for (int w = 0; w < 8; w++) { v0 += warp_sums[0][w]; v1 += warp_sums[1][w]; }
        // sums >= 0: float bits monotone as unsigned
        atomicMax(&g_img_max[img], __float_as_uint(v0));
        atomicMax(&g_img_max[img], __float_as_uint(v1));
        __threadfence();
        unsigned int old = atomicAdd(&g_counter, 1u);
        s_is_last = ((old % NBLOCKS) == (NBLOCKS - 1));
    }
    __syncthreads();

    if (s_is_last) {
        __threadfence();
        __shared__ float red[2];
        if (wid < 2) {
            int i = wid * 32 + lane;                     // 0..63
            unsigned int bits = atomicOr(&g_img_max[i], 0u);
            float m = __uint_as_float(bits);
#pragma unroll
            for (int s = 16; s > 0; s >>= 1)
                m += __shfl_xor_sync(0xFFFFFFFFu, m, s);
            if (lane == 0) red[wid] = m;
        }
        __syncthreads();
        if (tid == 0)
            *out = (red[0] + red[1]) * (1.0f / (float)PATCH_ELEMS / (float)B);
        __syncthreads();
        if (tid < B) g_img_max[tid] = 0u;   // reset for next replay
    }
}

extern "C" void kernel_launch(void* const* d_in, const int* in_sizes, int n_in,
                              void* d_out, int out_size)
{
    const float* o = (const float*)d_in[0];
    const float* t = (const float*)d_in[1];
    float* out = (float*)d_out;
    patch_loss_pair_kernel<<<NBLOCKS, 256>>>(o, t, out);
}